// round 17
// baseline (speedup 1.0000x reference)
#include <cuda_runtime.h>
#include <cuda_bf16.h>
#include <cuda_fp16.h>
#include <cstdint>

#define B_SZ  512
#define NIN   1024
#define NMID  8192
#define NOUT  1000
#define MPAD  1024
#define FAN   64
#define NCOND 2

// GEMM tiling: all-bf16 operands, cp.async 3-stage pipeline
#define TBM 128
#define TBN 128
#define TBK 16            // K elems per stage chunk
#define ROWB 48           // bf16 row stride bytes (32B data + 16B pad; conflict-free)
#define STAGE 3
#define OP_BYTES (128 * ROWB)            // 6144 per operand tile
#define STAGE_BYTES (4 * OP_BYTES)       // Ah, Al, Bh, Bl
#define GEMM_SMEM (STAGE * STAGE_BYTES)  // 73728
#define GEMM_THREADS 256

// ---------------------------------------------------------------------------
// Scratch (static device globals; referenced ONLY inside device code --
// passing them as kernel args from host binds the host shadow, which on
// GB300/ATS silently reads zeros / writes host RAM: the R5/R6 bug)
// ---------------------------------------------------------------------------
__device__ float4 g_act0v[(size_t)NMID * B_SZ / 4];           // fp32 [o][b]
__device__ float4 g_act1v[(size_t)NMID * B_SZ / 4];           // fp32 [o][b]
__device__ uint4  g_pk[NCOND][(size_t)(FAN / 4) * NMID];      // cond meta: 4x (fp16 w | u16 idx)
__device__ __nv_bfloat16 g_wih[(size_t)NMID * NIN],  g_wil[(size_t)NMID * NIN];
__device__ __nv_bfloat16 g_xh[(size_t)B_SZ * NIN],   g_xl[(size_t)B_SZ * NIN];
__device__ __nv_bfloat16 g_woh[(size_t)MPAD * NMID], g_wol[(size_t)MPAD * NMID];
__device__ __nv_bfloat16 g_a1h[(size_t)B_SZ * NMID], g_a1l[(size_t)B_SZ * NMID];

// ---------------------------------------------------------------------------
__device__ __forceinline__ void mma16816(float* d,
                                         uint32_t a0, uint32_t a1, uint32_t a2, uint32_t a3,
                                         uint32_t b0, uint32_t b1) {
    asm volatile(
        "mma.sync.aligned.m16n8k16.row.col.f32.bf16.bf16.f32 "
        "{%0,%1,%2,%3}, {%4,%5,%6,%7}, {%8,%9}, {%0,%1,%2,%3};"
        : "+f"(d[0]), "+f"(d[1]), "+f"(d[2]), "+f"(d[3])
        : "r"(a0), "r"(a1), "r"(a2), "r"(a3), "r"(b0), "r"(b1));
}
__device__ __forceinline__ void cp_async16(uint32_t dst, const void* src) {
    asm volatile("cp.async.cg.shared.global [%0], [%1], 16;" :: "r"(dst), "l"(src) : "memory");
}
__device__ __forceinline__ void cp_commit() {
    asm volatile("cp.async.commit_group;" ::: "memory");
}
__device__ __forceinline__ void cp_wait1() {
    asm volatile("cp.async.wait_group 1;" ::: "memory");
}

__device__ __forceinline__ void split_bf16(float v, __nv_bfloat16& h, __nv_bfloat16& l) {
    h = __float2bfloat16(v);
    l = __float2bfloat16(v - __bfloat162float(h));
}
__device__ __forceinline__ void split4(float4 v, ushort4& hv, ushort4& lv) {
    __nv_bfloat16 h0, h1, h2, h3, l0, l1, l2, l3;
    split_bf16(v.x, h0, l0); split_bf16(v.y, h1, l1);
    split_bf16(v.z, h2, l2); split_bf16(v.w, h3, l3);
    hv = make_ushort4(__bfloat16_as_ushort(h0), __bfloat16_as_ushort(h1),
                      __bfloat16_as_ushort(h2), __bfloat16_as_ushort(h3));
    lv = make_ushort4(__bfloat16_as_ushort(l0), __bfloat16_as_ushort(l1),
                      __bfloat16_as_ushort(l2), __bfloat16_as_ushort(l3));
}

// ---------------------------------------------------------------------------
// prep: hi/lo bf16 splits. WHICH 0: Win [NMID,NIN]; 1: x [B_SZ,NIN];
//                          WHICH 2: Wout [MPAD,NMID] (rows >= NOUT zeroed)
// ---------------------------------------------------------------------------
template <int WHICH>
__global__ void prep_split_kernel(const float* __restrict__ src) {
    constexpr int K       = (WHICH == 2) ? NMID : NIN;
    constexpr int rowsTot = (WHICH == 0) ? NMID : (WHICH == 1) ? B_SZ : MPAD;
    constexpr int rowsVal = (WHICH == 2) ? NOUT : rowsTot;
    __nv_bfloat16* dh = (WHICH == 0) ? g_wih : (WHICH == 1) ? g_xh : g_woh;
    __nv_bfloat16* dl = (WHICH == 0) ? g_wil : (WHICH == 1) ? g_xl : g_wol;

    long long t = blockIdx.x * (long long)blockDim.x + threadIdx.x;
    if (t * 4 >= (long long)rowsTot * K) return;
    int row = (int)((t * 4) / K);
    float4 v = (row < rowsVal) ? __ldg((const float4*)(src) + t)
                               : make_float4(0.f, 0.f, 0.f, 0.f);
    ushort4 hv, lv;
    split4(v, hv, lv);
    ((ushort4*)dh)[t] = hv;
    ((ushort4*)dl)[t] = lv;
}

// cond meta: pack (fp16 w | u16 idx) into one uint per f; uint4 = 4 f's
__global__ void prep_pk_kernel(const float* __restrict__ Wmid, const int* __restrict__ idx) {
    int t = blockIdx.x * blockDim.x + threadIdx.x;
    if (t >= NCOND * (FAN / 4) * NMID) return;
    int phase = t / ((FAN / 4) * NMID);
    int rem = t - phase * (FAN / 4) * NMID;
    int g4 = rem / NMID, o = rem - g4 * NMID;
    const float* wsrc = Wmid + (size_t)(phase * NMID + o) * FAN + g4 * 4;
    const int*   isrc = idx + (size_t)o * FAN + g4 * 4;
    uint4 v;
    v.x = (unsigned)(isrc[0] & (NMID - 1)) |
          ((uint32_t)__half_as_ushort(__float2half_rn(wsrc[0])) << 16);
    v.y = (unsigned)(isrc[1] & (NMID - 1)) |
          ((uint32_t)__half_as_ushort(__float2half_rn(wsrc[1])) << 16);
    v.z = (unsigned)(isrc[2] & (NMID - 1)) |
          ((uint32_t)__half_as_ushort(__float2half_rn(wsrc[2])) << 16);
    v.w = (unsigned)(isrc[3] & (NMID - 1)) |
          ((uint32_t)__half_as_ushort(__float2half_rn(wsrc[3])) << 16);
    g_pk[phase][(size_t)g4 * NMID + o] = v;
}

// ---------------------------------------------------------------------------
// all-bf16 warp-MMA GEMM, cp.async 3-stage, one sync per iter:
//   D[m][n] = Ah*Bh + Ah*Bl + Al*Bh  (pre-split operands, no in-loop cvt)
// MODE 0: A=g_wih/l B=g_xh/l,  Ks=NIN,  out: g_act0[m*B_SZ+n]=relu(D+bias[m])
// MODE 1: A=g_woh/l B=g_a1h/l, Ks=NMID, out: atomicAdd(out[n*NOUT+m], D)
// ---------------------------------------------------------------------------
template <int MODE>
__global__ __launch_bounds__(GEMM_THREADS) void mma_gemm(
    const float* __restrict__ bias, float* __restrict__ outp, int kIters)
{
    const __nv_bfloat16* __restrict__ Ah = (MODE == 0) ? g_wih : g_woh;
    const __nv_bfloat16* __restrict__ Al = (MODE == 0) ? g_wil : g_wol;
    const __nv_bfloat16* __restrict__ Bh = (MODE == 0) ? g_xh : g_a1h;
    const __nv_bfloat16* __restrict__ Bl = (MODE == 0) ? g_xl : g_a1l;
    float* out = (MODE == 0) ? (float*)g_act0v : outp;
    const int Ks = (MODE == 0) ? NIN : NMID;

    extern __shared__ char sm[];
    uint32_t smBase = (uint32_t)__cvta_generic_to_shared(sm);

    int tid = threadIdx.x;
    int wid = tid >> 5, lid = tid & 31;
    int g = lid >> 2, t = lid & 3;
    int wm = (wid >> 1) * 32;
    int wn = (wid & 1) * 64;
    int m0 = blockIdx.y * TBM;
    int n0 = blockIdx.x * TBN;
    int kk0 = blockIdx.z * kIters * TBK;

    // staging: per operand 128 rows x 32B = 256 chunks of 16B; 1 chunk/thread/operand
    int row = tid >> 1, seg = tid & 1;     // seg: 0/1 -> 16B halves
    uint32_t dstOff = (uint32_t)(row * ROWB + seg * 16);
    size_t srcOff = (size_t)row * Ks + seg * 8;    // elements

#define ISSUE_STAGE(it, p)                                                          \
    do {                                                                            \
        int kk = kk0 + (it) * TBK;                                                  \
        uint32_t b = smBase + (p) * STAGE_BYTES + dstOff;                           \
        cp_async16(b,                Ah + (size_t)m0 * Ks + srcOff + kk);           \
        cp_async16(b + OP_BYTES,     Al + (size_t)m0 * Ks + srcOff + kk);           \
        cp_async16(b + 2 * OP_BYTES, Bh + (size_t)n0 * Ks + srcOff + kk);           \
        cp_async16(b + 3 * OP_BYTES, Bl + (size_t)n0 * Ks + srcOff + kk);           \
    } while (0)

    float acc[2][8][4] = {};

    // prologue: STAGE-1 groups
#pragma unroll
    for (int s = 0; s < STAGE - 1; s++) {
        if (s < kIters) ISSUE_STAGE(s, s);
        cp_commit();
    }

    int koff = 4 * t;                       // byte offset in 32B bf16 row
    for (int it = 0; it < kIters; it++) {
        int p = it % STAGE;
        cp_wait1();                         // oldest group (stage p) done
        __syncthreads();                    // all threads' stage-p data visible

        const char* pAh = sm + p * STAGE_BYTES;
        const char* pAl = pAh + OP_BYTES;
        const char* pBh = pAh + 2 * OP_BYTES;
        const char* pBl = pAh + 3 * OP_BYTES;

        uint32_t a[2][4];
        // ---- aH fragments (reused across Bh and Bl passes) ----
#pragma unroll
        for (int mi = 0; mi < 2; mi++) {
            const char* base = pAh + (wm + mi * 16 + g) * ROWB + koff;
            a[mi][0] = *(const uint32_t*)(base);
            a[mi][1] = *(const uint32_t*)(base + 8 * ROWB);
            a[mi][2] = *(const uint32_t*)(base + 16);
            a[mi][3] = *(const uint32_t*)(base + 8 * ROWB + 16);
        }
#pragma unroll
        for (int nj = 0; nj < 4; nj++) {
            const char* bbh = pBh + (wn + nj * 16 + g) * ROWB + koff;
            const char* bbl = pBl + (wn + nj * 16 + g) * ROWB + koff;
            uint32_t bh0 = *(const uint32_t*)(bbh);
            uint32_t bh1 = *(const uint32_t*)(bbh + 16);
            uint32_t bh2 = *(const uint32_t*)(bbh + 8 * ROWB);
            uint32_t bh3 = *(const uint32_t*)(bbh + 8 * ROWB + 16);
            uint32_t bl0 = *(const uint32_t*)(bbl);
            uint32_t bl1 = *(const uint32_t*)(bbl + 16);
            uint32_t bl2 = *(const uint32_t*)(bbl + 8 * ROWB);
            uint32_t bl3 = *(const uint32_t*)(bbl + 8 * ROWB + 16);
#pragma unroll
            for (int mi = 0; mi < 2; mi++) {
                mma16816(acc[mi][nj * 2],     a[mi][0], a[mi][1], a[mi][2], a[mi][3], bh0, bh1);
                mma16816(acc[mi][nj * 2 + 1], a[mi][0], a[mi][1], a[mi][2], a[mi][3], bh2, bh3);
                mma16816(acc[mi][nj * 2],     a[mi][0], a[mi][1], a[mi][2], a[mi][3], bl0, bl1);
                mma16816(acc[mi][nj * 2 + 1], a[mi][0], a[mi][1], a[mi][2], a[mi][3], bl2, bl3);
            }
        }
        // ---- aL fragments, aL x bH pass ----
#pragma unroll
        for (int mi = 0; mi < 2; mi++) {
            const char* base = pAl + (wm + mi * 16 + g) * ROWB + koff;
            a[mi][0] = *(const uint32_t*)(base);
            a[mi][1] = *(const uint32_t*)(base + 8 * ROWB);
            a[mi][2] = *(const uint32_t*)(base + 16);
            a[mi][3] = *(const uint32_t*)(base + 8 * ROWB + 16);
        }
#pragma unroll
        for (int nj = 0; nj < 4; nj++) {
            const char* bbh = pBh + (wn + nj * 16 + g) * ROWB + koff;
            uint32_t b0 = *(const uint32_t*)(bbh);
            uint32_t b1 = *(const uint32_t*)(bbh + 16);
            uint32_t b2 = *(const uint32_t*)(bbh + 8 * ROWB);
            uint32_t b3 = *(const uint32_t*)(bbh + 8 * ROWB + 16);
#pragma unroll
            for (int mi = 0; mi < 2; mi++) {
                mma16816(acc[mi][nj * 2],     a[mi][0], a[mi][1], a[mi][2], a[mi][3], b0, b1);
                mma16816(acc[mi][nj * 2 + 1], a[mi][0], a[mi][1], a[mi][2], a[mi][3], b2, b3);
            }
        }

        // issue stage it+STAGE-1 into buffer (it+STAGE-1)%STAGE (old, post-sync safe);
        // ALWAYS commit so wait_group counting stays uniform through the tail
        if (it + STAGE - 1 < kIters) ISSUE_STAGE(it + STAGE - 1, (it + STAGE - 1) % STAGE);
        cp_commit();
    }
#undef ISSUE_STAGE

    // epilogue: c0,c1 at (m, n=2t), c2,c3 at (m+8, n=2t)
    int mrow = g;
    int ncol = t * 2;
#pragma unroll
    for (int mi = 0; mi < 2; mi++) {
        int m = m0 + wm + mi * 16 + mrow;
        if (MODE == 0) {
            float bv0 = bias[m], bv8 = bias[m + 8];
#pragma unroll
            for (int n8 = 0; n8 < 8; n8++) {
                int n = n0 + wn + n8 * 8 + ncol;
                float* c = acc[mi][n8];
                float2 lo = make_float2(fmaxf(c[0] + bv0, 0.f), fmaxf(c[1] + bv0, 0.f));
                float2 hi = make_float2(fmaxf(c[2] + bv8, 0.f), fmaxf(c[3] + bv8, 0.f));
                *(float2*)(out + (size_t)m * B_SZ + n) = lo;
                *(float2*)(out + (size_t)(m + 8) * B_SZ + n) = hi;
            }
        } else {
#pragma unroll
            for (int n8 = 0; n8 < 8; n8++) {
                int n = n0 + wn + n8 * 8 + ncol;
                float* c = acc[mi][n8];
                if (m < NOUT) {
                    atomicAdd(out + (size_t)n * NOUT + m, c[0]);
                    atomicAdd(out + (size_t)(n + 1) * NOUT + m, c[1]);
                }
                if (m + 8 < NOUT) {
                    atomicAdd(out + (size_t)n * NOUT + m + 8, c[2]);
                    atomicAdd(out + (size_t)(n + 1) * NOUT + m + 8, c[3]);
                }
            }
        }
    }
}

// ---------------------------------------------------------------------------
// Condensed layer (R16-proven: fp16 smem staging + packed fp16w|u16idx meta).
// phase 0: fp32 [o][b] -> fp32 [o][b]
// phase 1: fp32 [o][b] -> bf16 hi/lo [b][o] (g_a1h/g_a1l) for GEMM3
// ---------------------------------------------------------------------------
__global__ __launch_bounds__(1024) void cond_kernel(int phase, const float* __restrict__ bias) {
    extern __shared__ uint2 hsh[];   // [NMID], 4 halves each
    const float4* hin = (phase == 0) ? g_act0v : g_act1v;
    const uint4* pk = g_pk[phase];
    int bq = blockIdx.x;
    int b0 = bq * 4;
    int tid = threadIdx.x;

    for (int j = tid; j < NMID; j += 1024) {
        float4 v = hin[(size_t)j * (B_SZ / 4) + bq];
        __half2 p01 = __floats2half2_rn(v.x, v.y);
        __half2 p23 = __floats2half2_rn(v.z, v.w);
        uint2 u;
        u.x = *(uint32_t*)&p01;
        u.y = *(uint32_t*)&p23;
        hsh[j] = u;
    }
    __syncthreads();

#pragma unroll
    for (int oi = 0; oi < NMID / 1024; oi++) {
        int o = oi * 1024 + tid;
        float ax = 0.f, ay = 0.f, az = 0.f, aw = 0.f;
#pragma unroll
        for (int g = 0; g < FAN / 8; g++) {
            uint4 m0 = pk[(size_t)(2 * g) * NMID + o];
            uint4 m1 = pk[(size_t)(2 * g + 1) * NMID + o];
#define ACC(u)                                                              \
            {                                                               \
                uint2 p = hsh[(u) & 0xffff];                                \
                float wv = __half2float(__ushort_as_half(                   \
                               (unsigned short)((u) >> 16)));               \
                float2 f01 = __half22float2(*(__half2*)&p.x);               \
                float2 f23 = __half22float2(*(__half2*)&p.y);               \
                ax = fmaf(wv, f01.x, ax); ay = fmaf(wv, f01.y, ay);         \
                az = fmaf(wv, f23.x, az); aw = fmaf(wv, f23.y, aw);         \
            }
            ACC(m0.x) ACC(m0.y) ACC(m0.z) ACC(m0.w)
            ACC(m1.x) ACC(m1.y) ACC(m1.z) ACC(m1.w)
#undef ACC
        }
        float bv = bias[o];
        float4 r;
        r.x = fmaxf(ax + bv, 0.f); r.y = fmaxf(ay + bv, 0.f);
        r.z = fmaxf(az + bv, 0.f); r.w = fmaxf(aw + bv, 0.f);
        if (phase == 0) {
            g_act1v[(size_t)o * (B_SZ / 4) + bq] = r;
        } else {
            float vv[4] = {r.x, r.y, r.z, r.w};
#pragma unroll
            for (int i = 0; i < 4; i++) {
                __nv_bfloat16 h, l;
                split_bf16(vv[i], h, l);
                g_a1h[(size_t)(b0 + i) * NMID + o] = h;
                g_a1l[(size_t)(b0 + i) * NMID + o] = l;
            }
        }
    }
}

// ---------------------------------------------------------------------------
__global__ void init_out_kernel(const float* __restrict__ bout, float* __restrict__ out) {
    int t = blockIdx.x * blockDim.x + threadIdx.x;
    if (t < B_SZ * NOUT) out[t] = bout[t % NOUT];
}

// ---------------------------------------------------------------------------
extern "C" void kernel_launch(void* const* d_in, const int* in_sizes, int n_in,
                              void* d_out, int out_size) {
    const float* x    = (const float*)d_in[0];
    const float* Win  = (const float*)d_in[1];
    const float* bin  = (const float*)d_in[2];
    const float* Wmid = (const float*)d_in[3];
    const float* bmid = (const float*)d_in[4];
    const float* Wout = (const float*)d_in[5];
    const float* bout = (const float*)d_in[6];
    const int*   idx  = (const int*)d_in[7];    // int32 (JAX x64 disabled)
    float* out = (float*)d_out;

    cudaFuncSetAttribute(cond_kernel, cudaFuncAttributeMaxDynamicSharedMemorySize, 65536);
    cudaFuncSetAttribute(mma_gemm<0>, cudaFuncAttributeMaxDynamicSharedMemorySize, GEMM_SMEM);
    cudaFuncSetAttribute(mma_gemm<1>, cudaFuncAttributeMaxDynamicSharedMemorySize, GEMM_SMEM);

    // prep (scratch globals bound inside device code)
    prep_pk_kernel<<<(NCOND * (FAN / 4) * NMID + 255) / 256, 256>>>(Wmid, idx);
    prep_split_kernel<0><<<((size_t)NMID * NIN / 4 + 255) / 256, 256>>>(Win);
    prep_split_kernel<1><<<((size_t)B_SZ * NIN / 4 + 255) / 256, 256>>>(x);
    prep_split_kernel<2><<<((size_t)MPAD * NMID / 4 + 255) / 256, 256>>>(Wout);

    // GEMM1: relu(W_in x^T + b_in) -> g_act0 fp32 [o][b]
    mma_gemm<0><<<dim3(B_SZ / TBN, NMID / TBM, 1), GEMM_THREADS, GEMM_SMEM>>>(
        bin, nullptr, NIN / TBK);

    // condensed layers (4 batch cols per CTA, 128 CTAs, fp16 smem staging)
    cond_kernel<<<B_SZ / 4, 1024, 65536>>>(0, bmid);
    cond_kernel<<<B_SZ / 4, 1024, 65536>>>(1, bmid + NMID);

    // GEMM3: out[b][m] = act1 . W_out^T + b_out  (split-K=8, atomic)
    init_out_kernel<<<(B_SZ * NOUT + 255) / 256, 256>>>(bout, out);
    mma_gemm<1><<<dim3(B_SZ / TBN, MPAD / TBM, 8), GEMM_THREADS, GEMM_SMEM>>>(
        nullptr, out, NMID / (TBK * 8));
}